// round 1
// baseline (speedup 1.0000x reference)
#include <cuda_runtime.h>
#include <cstdint>

// ---------------------------------------------------------------------------
// PAM (position attention module), fp32 baseline.
//   q = X@Wb [BN,64], k = X@Wc [BN,64], v = X@Wd [BN,512]
//   out = gamma * softmax(q k^T) v + x     (per batch, N=4096 tokens)
// ---------------------------------------------------------------------------

#define B_   4
#define NTOK 4096
#define CC   512
#define CR   64
#define BN_TOT (B_ * NTOK)

// scratch (device globals: allowed; no cudaMalloc)
__device__ float g_q[B_ * NTOK * CR];
__device__ float g_k[B_ * NTOK * CR];
__device__ float g_v[B_ * NTOK * CC];

// ---------------------------------------------------------------------------
// Tiled GEMM: C[M,N] = A[M,K] @ B[K,N], row-major. BM=BN=64, BK=16, 256 thr.
// ---------------------------------------------------------------------------
__global__ __launch_bounds__(256) void gemm_kernel(
    const float* __restrict__ A, const float* __restrict__ Bm,
    float* __restrict__ C, int M, int N, int K) {
    __shared__ float As[16][68];   // transposed: As[k][m]
    __shared__ float Bs[16][64];
    int t = threadIdx.x;
    int bm = blockIdx.y * 64;
    int bn = blockIdx.x * 64;
    int tx = t & 15, ty = t >> 4;

    int arow = t >> 2;            // 0..63
    int akq  = (t & 3) * 4;       // 0,4,8,12
    int brow = t >> 4;            // 0..15
    int bcol = (t & 15) * 4;      // 0..60

    float acc[4][4] = {};

    for (int k0 = 0; k0 < K; k0 += 16) {
        float4 av = *(const float4*)&A[(size_t)(bm + arow) * K + k0 + akq];
        As[akq + 0][arow] = av.x;
        As[akq + 1][arow] = av.y;
        As[akq + 2][arow] = av.z;
        As[akq + 3][arow] = av.w;
        *(float4*)&Bs[brow][bcol] =
            *(const float4*)&Bm[(size_t)(k0 + brow) * N + bn + bcol];
        __syncthreads();
#pragma unroll
        for (int kk = 0; kk < 16; kk++) {
            float4 a4 = *(const float4*)&As[kk][ty * 4];
            float4 b4 = *(const float4*)&Bs[kk][tx * 4];
            float aa[4] = {a4.x, a4.y, a4.z, a4.w};
            float bb[4] = {b4.x, b4.y, b4.z, b4.w};
#pragma unroll
            for (int i = 0; i < 4; i++)
#pragma unroll
                for (int j = 0; j < 4; j++) acc[i][j] += aa[i] * bb[j];
        }
        __syncthreads();
    }
#pragma unroll
    for (int i = 0; i < 4; i++) {
        float4 o = make_float4(acc[i][0], acc[i][1], acc[i][2], acc[i][3]);
        *(float4*)&C[(size_t)(bm + ty * 4 + i) * N + bn + tx * 4] = o;
    }
}

// ---------------------------------------------------------------------------
// Fused flash-style attention + epilogue.
// CTA: 64 query rows of one batch. 512 threads. Online softmax over key
// blocks of 64. Accumulators: 8 rows x 8 cols per thread (fp32, registers).
// smem: qs[64][68] kT[64][68] ps[64][68] vs[64][512] m/l/f[64]
// ---------------------------------------------------------------------------
#define ATT_SMEM_FLOATS (3 * 64 * 68 + 64 * 512 + 3 * 64)
#define ATT_SMEM_BYTES  (ATT_SMEM_FLOATS * 4)

__global__ __launch_bounds__(512, 1) void attn_kernel(
    const float* __restrict__ q, const float* __restrict__ k,
    const float* __restrict__ v, const float* __restrict__ x,
    const float* __restrict__ gamma, float* __restrict__ out) {
    extern __shared__ float sm[];
    float* qs  = sm;                        // 64*68
    float* kT  = qs + 64 * 68;              // 64*68  (kT[d][c])
    float* ps  = kT + 64 * 68;              // 64*68
    float* vs  = ps + 64 * 68;              // 64*512
    float* msm = vs + 64 * 512;             // 64
    float* lsm = msm + 64;                  // 64
    float* fsm = lsm + 64;                  // 64

    const int t = threadIdx.x;
    const int b = blockIdx.y;
    const int row0 = blockIdx.x * 64;
    const size_t tokbase = (size_t)b * NTOK + row0;

    // load q tile [64 rows][64 dims]
    for (int i = t; i < 64 * 64; i += 512) {
        int r = i >> 6, d = i & 63;
        qs[r * 68 + d] = q[(tokbase + r) * CR + d];
    }
    if (t < 64) {
        msm[t] = __int_as_float(0xff800000);  // -inf
        lsm[t] = 0.f;
    }

    // score-phase mapping: thread -> (row sr, 8 cols starting sc0)
    const int sr  = t >> 3;
    const int scg = t & 7;
    const int sc0 = scg * 8;

    // accum-phase mapping: thread -> 8 rows (r0..) x 8 cols (c0..)
    const int r0 = (t >> 6) * 8;
    const int c0 = (t & 63) * 8;

    float acc[8][8];
#pragma unroll
    for (int i = 0; i < 8; i++)
#pragma unroll
        for (int j = 0; j < 8; j++) acc[i][j] = 0.f;

    __syncthreads();

    for (int jb = 0; jb < NTOK / 64; jb++) {
        // ---- load k tile (transposed) and v tile ----
        const size_t kvbase = (size_t)b * NTOK + (size_t)jb * 64;
        for (int i = t; i < 64 * 64; i += 512) {
            int c = i >> 6, d = i & 63;
            kT[d * 68 + c] = k[(kvbase + c) * CR + d];
        }
        {
            const float4* vg = (const float4*)&v[kvbase * CC];
            float4* vs4 = (float4*)vs;
            for (int i = t; i < 64 * (CC / 4); i += 512) vs4[i] = vg[i];
        }
        __syncthreads();

        // ---- scores: s[j] = q[sr] . k[sc0+j] ----
        float s[8];
#pragma unroll
        for (int j = 0; j < 8; j++) s[j] = 0.f;
#pragma unroll 4
        for (int d = 0; d < 64; d++) {
            float qv = qs[sr * 68 + d];
            float4 k0v = *(const float4*)&kT[d * 68 + sc0];
            float4 k1v = *(const float4*)&kT[d * 68 + sc0 + 4];
            s[0] += qv * k0v.x; s[1] += qv * k0v.y;
            s[2] += qv * k0v.z; s[3] += qv * k0v.w;
            s[4] += qv * k1v.x; s[5] += qv * k1v.y;
            s[6] += qv * k1v.z; s[7] += qv * k1v.w;
        }
        // row max over 8-lane group
        float bmx = s[0];
#pragma unroll
        for (int j = 1; j < 8; j++) bmx = fmaxf(bmx, s[j]);
        bmx = fmaxf(bmx, __shfl_xor_sync(0xffffffffu, bmx, 1));
        bmx = fmaxf(bmx, __shfl_xor_sync(0xffffffffu, bmx, 2));
        bmx = fmaxf(bmx, __shfl_xor_sync(0xffffffffu, bmx, 4));

        float mold = msm[sr];
        float mnew = fmaxf(mold, bmx);
        float lsum = 0.f;
#pragma unroll
        for (int j = 0; j < 8; j++) {
            s[j] = __expf(s[j] - mnew);
            lsum += s[j];
        }
        lsum += __shfl_xor_sync(0xffffffffu, lsum, 1);
        lsum += __shfl_xor_sync(0xffffffffu, lsum, 2);
        lsum += __shfl_xor_sync(0xffffffffu, lsum, 4);
        if (scg == 0) {
            float f = __expf(mold - mnew);
            fsm[sr] = f;
            lsm[sr] = lsm[sr] * f + lsum;
            msm[sr] = mnew;
        }
        *(float4*)&ps[sr * 68 + sc0]     = make_float4(s[0], s[1], s[2], s[3]);
        *(float4*)&ps[sr * 68 + sc0 + 4] = make_float4(s[4], s[5], s[6], s[7]);
        __syncthreads();

        // ---- rescale accumulators, then acc += P @ V ----
        float fr[8];
#pragma unroll
        for (int i = 0; i < 8; i++) fr[i] = fsm[r0 + i];
#pragma unroll
        for (int i = 0; i < 8; i++)
#pragma unroll
            for (int j = 0; j < 8; j++) acc[i][j] *= fr[i];

#pragma unroll 2
        for (int kk = 0; kk < 64; kk++) {
            float4 v0 = *(const float4*)&vs[kk * CC + c0];
            float4 v1 = *(const float4*)&vs[kk * CC + c0 + 4];
            float vv[8] = {v0.x, v0.y, v0.z, v0.w, v1.x, v1.y, v1.z, v1.w};
#pragma unroll
            for (int i = 0; i < 8; i++) {
                float p = ps[(r0 + i) * 68 + kk];
#pragma unroll
                for (int j = 0; j < 8; j++) acc[i][j] += p * vv[j];
            }
        }
        __syncthreads();
    }

    // ---- epilogue: out = gamma * acc / l + x ----
    const float g = gamma[0];
#pragma unroll
    for (int i = 0; i < 8; i++) {
        int r = r0 + i;
        float linv = 1.f / lsm[r];
        size_t off = (tokbase + r) * CC + c0;
        float4 x0 = *(const float4*)&x[off];
        float4 x1 = *(const float4*)&x[off + 4];
        float4 o0, o1;
        o0.x = g * acc[i][0] * linv + x0.x;
        o0.y = g * acc[i][1] * linv + x0.y;
        o0.z = g * acc[i][2] * linv + x0.z;
        o0.w = g * acc[i][3] * linv + x0.w;
        o1.x = g * acc[i][4] * linv + x1.x;
        o1.y = g * acc[i][5] * linv + x1.y;
        o1.z = g * acc[i][6] * linv + x1.z;
        o1.w = g * acc[i][7] * linv + x1.w;
        *(float4*)&out[off]     = o0;
        *(float4*)&out[off + 4] = o1;
    }
}

// ---------------------------------------------------------------------------
extern "C" void kernel_launch(void* const* d_in, const int* in_sizes, int n_in,
                              void* d_out, int out_size) {
    const float* x     = (const float*)d_in[0];
    const float* Wb    = (const float*)d_in[1];
    const float* Wc    = (const float*)d_in[2];
    const float* Wd    = (const float*)d_in[3];
    const float* gamma = (const float*)d_in[4];
    float* out = (float*)d_out;

    float *qp, *kp, *vp;
    cudaGetSymbolAddress((void**)&qp, g_q);
    cudaGetSymbolAddress((void**)&kp, g_k);
    cudaGetSymbolAddress((void**)&vp, g_v);

    cudaFuncSetAttribute(attn_kernel,
                         cudaFuncAttributeMaxDynamicSharedMemorySize,
                         ATT_SMEM_BYTES);

    // q = X @ Wb   (M=16384, N=64, K=512)
    gemm_kernel<<<dim3(1, BN_TOT / 64), 256>>>(x, Wb, qp, BN_TOT, CR, CC);
    // k = X @ Wc
    gemm_kernel<<<dim3(1, BN_TOT / 64), 256>>>(x, Wc, kp, BN_TOT, CR, CC);
    // v = X @ Wd   (M=16384, N=512, K=512)
    gemm_kernel<<<dim3(CC / 64, BN_TOT / 64), 256>>>(x, Wd, vp, BN_TOT, CC, CC);
    // fused attention + residual epilogue
    attn_kernel<<<dim3(NTOK / 64, B_), 512, ATT_SMEM_BYTES>>>(
        qp, kp, vp, x, gamma, out);
}